// round 1
// baseline (speedup 1.0000x reference)
#include <cuda_runtime.h>

// ComplexScaling: separable bilinear grid_sample with uniform scaling
// s = 1 + theta[0], align_corners=False, zeros padding.
// input: [N=32, H=1024, W=1024, C=2] fp32 NHWC; output same shape.
// C=2 -> treat each pixel as float2.

#define HH 1024
#define WW 1024

__global__ __launch_bounds__(256)
void complex_scaling_kernel(const float2* __restrict__ in,
                            const float* __restrict__ theta,
                            float2* __restrict__ out)
{
    const int j = blockIdx.x * blockDim.x + threadIdx.x;  // output column
    const int i = blockIdx.y;                              // output row
    const int n = blockIdx.z;                              // image

    const float s = 1.0f + __ldg(theta);

    // normalized coords, align_corners=False
    const float xn = (2.0f * (float)j + 1.0f) * (1.0f / (float)WW) - 1.0f;
    const float yn = (2.0f * (float)i + 1.0f) * (1.0f / (float)HH) - 1.0f;
    const float ix = ((s * xn + 1.0f) * (float)WW - 1.0f) * 0.5f;
    const float iy = ((s * yn + 1.0f) * (float)HH - 1.0f) * 0.5f;

    const float fx0 = floorf(ix);
    const float fy0 = floorf(iy);
    const float wx1 = ix - fx0;
    const float wx0 = 1.0f - wx1;
    const float wy1 = iy - fy0;
    const float wy0 = 1.0f - wy1;

    const int x0 = (int)fx0;
    const int x1 = x0 + 1;
    const int y0 = (int)fy0;
    const int y1 = y0 + 1;

    // zeros padding: out-of-range corner -> weight 0; index clamped for safety
    const float mwx0 = (x0 >= 0 && x0 < WW) ? wx0 : 0.0f;
    const float mwx1 = (x1 >= 0 && x1 < WW) ? wx1 : 0.0f;
    const float mwy0 = (y0 >= 0 && y0 < HH) ? wy0 : 0.0f;
    const float mwy1 = (y1 >= 0 && y1 < HH) ? wy1 : 0.0f;

    const int cx0 = min(max(x0, 0), WW - 1);
    const int cx1 = min(max(x1, 0), WW - 1);
    const int cy0 = min(max(y0, 0), HH - 1);
    const int cy1 = min(max(y1, 0), HH - 1);

    const float2* img = in + (size_t)n * (HH * WW);

    const float2 p00 = __ldg(img + (size_t)cy0 * WW + cx0);
    const float2 p01 = __ldg(img + (size_t)cy0 * WW + cx1);
    const float2 p10 = __ldg(img + (size_t)cy1 * WW + cx0);
    const float2 p11 = __ldg(img + (size_t)cy1 * WW + cx1);

    float2 r;
    // row interpolation along x, then along y
    const float r0x = mwx0 * p00.x + mwx1 * p01.x;
    const float r0y = mwx0 * p00.y + mwx1 * p01.y;
    const float r1x = mwx0 * p10.x + mwx1 * p11.x;
    const float r1y = mwx0 * p10.y + mwx1 * p11.y;
    r.x = mwy0 * r0x + mwy1 * r1x;
    r.y = mwy0 * r0y + mwy1 * r1y;

    out[(size_t)n * (HH * WW) + (size_t)i * WW + j] = r;
}

extern "C" void kernel_launch(void* const* d_in, const int* in_sizes, int n_in,
                              void* d_out, int out_size)
{
    const float2* in   = (const float2*)d_in[0];   // [32,1024,1024,2] fp32
    const float* theta = (const float*)d_in[1];    // [1] fp32
    float2* out        = (float2*)d_out;

    const int N = 32;
    dim3 block(256, 1, 1);
    dim3 grid(WW / 256, HH, N);
    complex_scaling_kernel<<<grid, block>>>(in, theta, out);
}

// round 2
// speedup vs baseline: 1.4326x; 1.4326x over previous
#include <cuda_runtime.h>

// ComplexScaling: separable bilinear grid_sample, s = 1 + theta[0],
// align_corners=False, zeros padding. input [32,1024,1024,2] fp32 NHWC.
// C=2 -> pixel = float2. Each thread handles 2 adjacent pixels (float4).
//
// Fast path: when the sampling coordinates are exact integers in-range
// (true whenever s == 1, i.e. theta == 0), the op is an identity copy;
// do a single 16B load + 16B store. Generic 4-corner bilinear otherwise.

#define HH 1024
#define WW 1024

__device__ __forceinline__ float2 sample_pixel(const float2* __restrict__ img,
                                               int j, float s)
{
    const float xn = (2.0f * (float)j + 1.0f) * (1.0f / (float)WW) - 1.0f;
    const float ix = ((s * xn + 1.0f) * (float)WW - 1.0f) * 0.5f;
    const float fx0 = floorf(ix);
    const float wx1 = ix - fx0;
    const float wx0 = 1.0f - wx1;
    const int x0 = (int)fx0;
    const int x1 = x0 + 1;
    const float mwx0 = (x0 >= 0 && x0 < WW) ? wx0 : 0.0f;
    const float mwx1 = (x1 >= 0 && x1 < WW) ? wx1 : 0.0f;
    const int cx0 = min(max(x0, 0), WW - 1);
    const int cx1 = min(max(x1, 0), WW - 1);
    // y handled by caller via weights in img pointers? No: caller passes rows.
    return make_float2(mwx0, mwx1), make_float2((float)cx0, (float)cx1); // unused
}

__global__ __launch_bounds__(256)
void complex_scaling_kernel(const float2* __restrict__ in,
                            const float* __restrict__ theta,
                            float2* __restrict__ out)
{
    const int t = blockIdx.x * blockDim.x + threadIdx.x;  // pixel-pair index
    const int i = blockIdx.y;                              // output row
    const int n = blockIdx.z;                              // image
    const int j0 = t * 2;
    const int j1 = j0 + 1;

    const float s = 1.0f + __ldg(theta);

    // ---- y coords (uniform per block) ----
    const float yn  = (2.0f * (float)i + 1.0f) * (1.0f / (float)HH) - 1.0f;
    const float iy  = ((s * yn + 1.0f) * (float)HH - 1.0f) * 0.5f;
    const float fy0 = floorf(iy);
    const float wy1 = iy - fy0;
    const float wy0 = 1.0f - wy1;
    const int y0 = (int)fy0;
    const int y1 = y0 + 1;

    // ---- x coords for the two pixels ----
    const float xn0 = (2.0f * (float)j0 + 1.0f) * (1.0f / (float)WW) - 1.0f;
    const float xn1 = (2.0f * (float)j1 + 1.0f) * (1.0f / (float)WW) - 1.0f;
    const float ixa = ((s * xn0 + 1.0f) * (float)WW - 1.0f) * 0.5f;
    const float ixb = ((s * xn1 + 1.0f) * (float)WW - 1.0f) * 0.5f;
    const float fxa0 = floorf(ixa);
    const float fxb0 = floorf(ixb);
    const float wxa1 = ixa - fxa0;
    const float wxb1 = ixb - fxb0;
    const int xa0 = (int)fxa0;
    const int xb0 = (int)fxb0;

    const float2* img = in + (size_t)n * (HH * WW);
    const size_t obase = (size_t)n * (HH * WW) + (size_t)i * WW + j0;

    // ---- fast path: exact integer sample coords, in range, vectorizable ----
    const bool fast = (wy1 == 0.0f) & (y0 >= 0) & (y0 < HH)
                    & (wxa1 == 0.0f) & (wxb1 == 0.0f)
                    & (xa0 >= 0) & (xb0 < WW)
                    & (xb0 == xa0 + 1) & ((xa0 & 1) == 0);

    if (fast) {
        const float4 v = *reinterpret_cast<const float4*>(img + (size_t)y0 * WW + xa0);
        *reinterpret_cast<float4*>(out + obase) = v;
        return;
    }

    // ---- generic bilinear path ----
    const float wxa0 = 1.0f - wxa1;
    const float wxb0 = 1.0f - wxb1;
    const int xa1 = xa0 + 1;
    const int xb1 = xb0 + 1;

    const float mwy0 = (y0 >= 0 && y0 < HH) ? wy0 : 0.0f;
    const float mwy1 = (y1 >= 0 && y1 < HH) ? wy1 : 0.0f;
    const int cy0 = min(max(y0, 0), HH - 1);
    const int cy1 = min(max(y1, 0), HH - 1);

    const float mwxa0 = (xa0 >= 0 && xa0 < WW) ? wxa0 : 0.0f;
    const float mwxa1 = (xa1 >= 0 && xa1 < WW) ? wxa1 : 0.0f;
    const float mwxb0 = (xb0 >= 0 && xb0 < WW) ? wxb0 : 0.0f;
    const float mwxb1 = (xb1 >= 0 && xb1 < WW) ? wxb1 : 0.0f;
    const int cxa0 = min(max(xa0, 0), WW - 1);
    const int cxa1 = min(max(xa1, 0), WW - 1);
    const int cxb0 = min(max(xb0, 0), WW - 1);
    const int cxb1 = min(max(xb1, 0), WW - 1);

    const float2* r0 = img + (size_t)cy0 * WW;
    const float2* r1 = img + (size_t)cy1 * WW;

    // pixel a
    const float2 a00 = __ldg(r0 + cxa0);
    const float2 a01 = __ldg(r0 + cxa1);
    const float2 a10 = __ldg(r1 + cxa0);
    const float2 a11 = __ldg(r1 + cxa1);
    // pixel b
    const float2 b00 = __ldg(r0 + cxb0);
    const float2 b01 = __ldg(r0 + cxb1);
    const float2 b10 = __ldg(r1 + cxb0);
    const float2 b11 = __ldg(r1 + cxb1);

    float4 res;
    {
        const float r0x = mwxa0 * a00.x + mwxa1 * a01.x;
        const float r0y = mwxa0 * a00.y + mwxa1 * a01.y;
        const float r1x = mwxa0 * a10.x + mwxa1 * a11.x;
        const float r1y = mwxa0 * a10.y + mwxa1 * a11.y;
        res.x = mwy0 * r0x + mwy1 * r1x;
        res.y = mwy0 * r0y + mwy1 * r1y;
    }
    {
        const float r0x = mwxb0 * b00.x + mwxb1 * b01.x;
        const float r0y = mwxb0 * b00.y + mwxb1 * b01.y;
        const float r1x = mwxb0 * b10.x + mwxb1 * b11.x;
        const float r1y = mwxb0 * b10.y + mwxb1 * b11.y;
        res.z = mwy0 * r0x + mwy1 * r1x;
        res.w = mwy0 * r0y + mwy1 * r1y;
    }
    *reinterpret_cast<float4*>(out + obase) = res;
}

extern "C" void kernel_launch(void* const* d_in, const int* in_sizes, int n_in,
                              void* d_out, int out_size)
{
    const float2* in   = (const float2*)d_in[0];   // [32,1024,1024,2] fp32
    const float* theta = (const float*)d_in[1];    // [1] fp32
    float2* out        = (float2*)d_out;

    const int N = 32;
    dim3 block(256, 1, 1);
    dim3 grid((WW / 2) / 256, HH, N);              // 2 x 1024 x 32
    complex_scaling_kernel<<<grid, block>>>(in, theta, out);
}